// round 13
// baseline (speedup 1.0000x reference)
#include <cuda_runtime.h>
#include <cuda_bf16.h>
#include <math.h>
#include <cstdint>

#define NAGT 1024
#define RNN  128
#define NMIX 20

typedef unsigned long long ull;
typedef unsigned int uint;

// ---------------- device scratch ----------------
__device__ float g_Hs[NAGT * 4096];          // Hs[m][g*64+e], 16 MB
__device__ float g_gatesB[NAGT * 512];       // h0 @ W_hh^T
__device__ float g_WihT[128 * 512];          // WihT[k][c] = W_ih[c][k]

// ================= bf16-split helpers ====================================
__device__ __forceinline__ uint pack_hi2(float x, float y, float& lx, float& ly) {
    __nv_bfloat16 hx = __float2bfloat16(x);
    __nv_bfloat16 hy = __float2bfloat16(y);
    lx = x - __bfloat162float(hx);
    ly = y - __bfloat162float(hy);
    __nv_bfloat162 h; h.x = hx; h.y = hy;
    return *(uint*)&h;
}
__device__ __forceinline__ uint pack2(float x, float y) {
    __nv_bfloat162 h; h.x = __float2bfloat16(x); h.y = __float2bfloat16(y);
    return *(uint*)&h;
}
__device__ __forceinline__ void mma16816(float* d, uint a0, uint a1, uint a2, uint a3,
                                         uint b0, uint b1) {
    asm volatile(
        "mma.sync.aligned.m16n8k16.row.col.f32.bf16.bf16.f32 "
        "{%0,%1,%2,%3}, {%4,%5,%6,%7}, {%8,%9}, {%0,%1,%2,%3};"
        : "+f"(d[0]), "+f"(d[1]), "+f"(d[2]), "+f"(d[3])
        : "r"(a0), "r"(a1), "r"(a2), "r"(a3), "r"(b0), "r"(b1));
}

// ---------------- MUFU.TANH-based nonlinearities ----------------
__device__ __forceinline__ float tanh_ap(float x) {
    float y;
    asm("tanh.approx.f32 %0, %1;" : "=f"(y) : "f"(x));
    return y;
}
__device__ __forceinline__ float sigmoid_ap(float x) {
    return fmaf(tanh_ap(0.5f * x), 0.5f, 0.5f);
}

// ================= Kernel A =====================================
// blocks 0..127: Hs tile 128m x 256n + gatesB slice 128m x 32n (tensor)
// blocks 128..135: Wih transpose slice (64 cols of WihT each)
#define HS_AROW 272
#define HS_A_HI 0
#define HS_A_LO (128 * HS_AROW)
#define HS_B_HI (2 * 128 * HS_AROW)
#define HS_B_LO (HS_B_HI + 256 * HS_AROW)
#define HS_SMEM (HS_B_LO + 256 * HS_AROW)   // 208896

__global__ void __launch_bounds__(512) kA(const float* __restrict__ h0,
                                          const float* __restrict__ Wsoc,
                                          const float* __restrict__ Whh,
                                          const float* __restrict__ Wih) {
    extern __shared__ __align__(16) char sm[];
    const int tid = threadIdx.x;

    if (blockIdx.x >= 128) {
        // ---- Wih transpose: block t -> WihT cols [64t, 64t+64) ----
        float* tile = (float*)sm;            // [64][130]
        const int t = blockIdx.x - 128;
#pragma unroll
        for (int p = 0; p < 4; p++) {
            int idx = tid + p * 512;         // 2048 float4 = 64 rows x 32 c4
            int r = idx >> 5, c4 = idx & 31;
            float4 v = *(const float4*)(Wih + (t * 64 + r) * 128 + c4 * 4);
            tile[r * 130 + c4 * 4 + 0] = v.x;
            tile[r * 130 + c4 * 4 + 1] = v.y;
            tile[r * 130 + c4 * 4 + 2] = v.z;
            tile[r * 130 + c4 * 4 + 3] = v.w;
        }
        __syncthreads();
#pragma unroll
        for (int p = 0; p < 16; p++) {
            int idx = tid + p * 512;         // 8192 = 128 k x 64 j
            int k = idx >> 6, j = idx & 63;
            g_WihT[k * 512 + t * 64 + j] = tile[j * 130 + k];
        }
        return;
    }

    const int wid = tid >> 5, lane = tid & 31;
    const int m0 = (blockIdx.x & 7) * 128;
    const int c0 = (blockIdx.x >> 3) * 256;

    // ---- fill A: h0 tile 128 x 128 -> bf16 hi/lo ----
#pragma unroll
    for (int p = 0; p < 8; p++) {
        int idx = tid + p * 512;
        int r = idx >> 5, c4 = idx & 31;
        float4 v = *(const float4*)(h0 + (m0 + r) * 128 + c4 * 4);
        float lx, ly, lz, lw;
        uint2 H, L;
        H.x = pack_hi2(v.x, v.y, lx, ly);
        H.y = pack_hi2(v.z, v.w, lz, lw);
        L.x = pack2(lx, ly);
        L.y = pack2(lz, lw);
        int off = r * HS_AROW + c4 * 8;
        *(uint2*)(sm + HS_A_HI + off) = H;
        *(uint2*)(sm + HS_A_LO + off) = L;
    }
    // ---- fill B: Wsoc-derived 256 x 128 ----
#pragma unroll
    for (int p = 0; p < 16; p++) {
        int idx = tid + p * 512;
        int r = idx >> 5, c4 = idx & 31;
        int gc = c0 + r;
        float4 v = *(const float4*)(Wsoc + (gc & 63) * 8192 + (gc >> 6) * 128 + c4 * 4);
        float lx, ly, lz, lw;
        uint2 H, L;
        H.x = pack_hi2(v.x, v.y, lx, ly);
        H.y = pack_hi2(v.z, v.w, lz, lw);
        L.x = pack2(lx, ly);
        L.y = pack2(lz, lw);
        int off = r * HS_AROW + c4 * 8;
        *(uint2*)(sm + HS_B_HI + off) = H;
        *(uint2*)(sm + HS_B_LO + off) = L;
    }
    __syncthreads();

    const int wm = (wid >> 2) * 32;
    const int wn = (wid & 3) * 64;
    const int tq = lane >> 2;
    const int tr = lane & 3;

    {
        float acc[2][8][4];
#pragma unroll
        for (int i = 0; i < 2; i++)
#pragma unroll
            for (int j = 0; j < 8; j++)
#pragma unroll
                for (int q = 0; q < 4; q++) acc[i][j][q] = 0.0f;

#pragma unroll 1
        for (int ks = 0; ks < 8; ks++) {
            const int kb = ks * 32 + tr * 4;
            uint aH[2][4], aL[2][4];
#pragma unroll
            for (int mf = 0; mf < 2; mf++) {
                int row = wm + mf * 16 + tq;
                int o0 = row * HS_AROW + kb;
                int o1 = o0 + 8 * HS_AROW;
                aH[mf][0] = *(const uint*)(sm + HS_A_HI + o0);
                aH[mf][1] = *(const uint*)(sm + HS_A_HI + o1);
                aH[mf][2] = *(const uint*)(sm + HS_A_HI + o0 + 16);
                aH[mf][3] = *(const uint*)(sm + HS_A_HI + o1 + 16);
                aL[mf][0] = *(const uint*)(sm + HS_A_LO + o0);
                aL[mf][1] = *(const uint*)(sm + HS_A_LO + o1);
                aL[mf][2] = *(const uint*)(sm + HS_A_LO + o0 + 16);
                aL[mf][3] = *(const uint*)(sm + HS_A_LO + o1 + 16);
            }
#pragma unroll
            for (int nf = 0; nf < 8; nf++) {
                int col = wn + nf * 8 + tq;
                int o0 = col * HS_AROW + kb;
                uint bH0 = *(const uint*)(sm + HS_B_HI + o0);
                uint bH1 = *(const uint*)(sm + HS_B_HI + o0 + 16);
                uint bL0 = *(const uint*)(sm + HS_B_LO + o0);
                uint bL1 = *(const uint*)(sm + HS_B_LO + o0 + 16);
#pragma unroll
                for (int mf = 0; mf < 2; mf++) {
                    mma16816(acc[mf][nf], aH[mf][0], aH[mf][1], aH[mf][2], aH[mf][3], bH0, bH1);
                    mma16816(acc[mf][nf], aH[mf][0], aH[mf][1], aH[mf][2], aH[mf][3], bL0, bL1);
                    mma16816(acc[mf][nf], aL[mf][0], aL[mf][1], aL[mf][2], aL[mf][3], bH0, bH1);
                }
            }
        }
#pragma unroll
        for (int mf = 0; mf < 2; mf++) {
            int row0 = m0 + wm + mf * 16 + tq;
#pragma unroll
            for (int nf = 0; nf < 8; nf++) {
                int col = c0 + wn + nf * 8 + tr * 2;
                *(float2*)&g_Hs[row0 * 4096 + col] =
                    make_float2(acc[mf][nf][0], acc[mf][nf][1]);
                *(float2*)&g_Hs[(row0 + 8) * 4096 + col] =
                    make_float2(acc[mf][nf][2], acc[mf][nf][3]);
            }
        }
    }

    // ---- phase 2: gatesB slice 128m x 32n ----
    __syncthreads();
    const int j0 = (blockIdx.x >> 3) * 32;
#pragma unroll
    for (int p = 0; p < 2; p++) {
        int idx = tid + p * 512;
        int r = idx >> 5, c4 = idx & 31;
        float4 v = *(const float4*)(Whh + (j0 + r) * 128 + c4 * 4);
        float lx, ly, lz, lw;
        uint2 H, L;
        H.x = pack_hi2(v.x, v.y, lx, ly);
        H.y = pack_hi2(v.z, v.w, lz, lw);
        L.x = pack2(lx, ly);
        L.y = pack2(lz, lw);
        int off = r * HS_AROW + c4 * 8;
        *(uint2*)(sm + HS_B_HI + off) = H;
        *(uint2*)(sm + HS_B_LO + off) = L;
    }
    __syncthreads();

    const int wn2 = (wid & 3) * 8;
    float acc2[2][4];
#pragma unroll
    for (int i = 0; i < 2; i++)
#pragma unroll
        for (int q = 0; q < 4; q++) acc2[i][q] = 0.0f;

#pragma unroll 1
    for (int ks = 0; ks < 8; ks++) {
        const int kb = ks * 32 + tr * 4;
        uint aH[2][4], aL[2][4];
#pragma unroll
        for (int mf = 0; mf < 2; mf++) {
            int row = wm + mf * 16 + tq;
            int o0 = row * HS_AROW + kb;
            int o1 = o0 + 8 * HS_AROW;
            aH[mf][0] = *(const uint*)(sm + HS_A_HI + o0);
            aH[mf][1] = *(const uint*)(sm + HS_A_HI + o1);
            aH[mf][2] = *(const uint*)(sm + HS_A_HI + o0 + 16);
            aH[mf][3] = *(const uint*)(sm + HS_A_HI + o1 + 16);
            aL[mf][0] = *(const uint*)(sm + HS_A_LO + o0);
            aL[mf][1] = *(const uint*)(sm + HS_A_LO + o1);
            aL[mf][2] = *(const uint*)(sm + HS_A_LO + o0 + 16);
            aL[mf][3] = *(const uint*)(sm + HS_A_LO + o1 + 16);
        }
        int col = wn2 + tq;
        int o0 = col * HS_AROW + kb;
        uint bH0 = *(const uint*)(sm + HS_B_HI + o0);
        uint bH1 = *(const uint*)(sm + HS_B_HI + o0 + 16);
        uint bL0 = *(const uint*)(sm + HS_B_LO + o0);
        uint bL1 = *(const uint*)(sm + HS_B_LO + o0 + 16);
#pragma unroll
        for (int mf = 0; mf < 2; mf++) {
            mma16816(acc2[mf], aH[mf][0], aH[mf][1], aH[mf][2], aH[mf][3], bH0, bH1);
            mma16816(acc2[mf], aH[mf][0], aH[mf][1], aH[mf][2], aH[mf][3], bL0, bL1);
            mma16816(acc2[mf], aL[mf][0], aL[mf][1], aL[mf][2], aL[mf][3], bH0, bH1);
        }
    }
#pragma unroll
    for (int mf = 0; mf < 2; mf++) {
        int row0 = m0 + wm + mf * 16 + tq;
        int col = j0 + wn2 + tr * 2;
        *(float2*)&g_gatesB[row0 * 512 + col] = make_float2(acc2[mf][0], acc2[mf][1]);
        *(float2*)&g_gatesB[(row0 + 8) * 512 + col] = make_float2(acc2[mf][2], acc2[mf][3]);
    }
}

// ================= mega kD: emb + pool + gatesA + LSTM + out =============
// grid=128 (8 agents each), 512 threads.
// smem float region layout (float offsets):
#define MG_SX    0                    // [1024]
#define MG_SY    1024                 // [1024]
#define MG_RED   2048                 // [16][64]
#define MG_XINT  3072                 // [128][8]  xinT[k][r]
#define MG_GATES 4096                 // [8][512]
#define MG_HN    8192                 // [8][128]
#define MG_WOT   9216                 // [128][121]
#define MG_FLOATS (MG_WOT + 128 * 121)        // 24704 floats
#define MG_LIST_OFF (MG_FLOATS * 4)           // byte offset of list
#define MG_SMEM (MG_LIST_OFF + 8 * 1024 * 2)  // + 16KB shorts = 115200 B
#define KD_WOT_PAD 121

__global__ void __launch_bounds__(512) kD(const float* __restrict__ c0v,
                                          const float* __restrict__ b_ih,
                                          const float* __restrict__ b_hh,
                                          const float* __restrict__ Wout,
                                          const float* __restrict__ b_out,
                                          const float* __restrict__ xoff,
                                          const float* __restrict__ xabs,
                                          const float* __restrict__ W_emb,
                                          const float* __restrict__ b_emb,
                                          const float* __restrict__ b_soc,
                                          float* __restrict__ out) {
    extern __shared__ __align__(16) float sf[];
    unsigned short* list = (unsigned short*)((char*)sf + MG_LIST_OFF);
    const int m0 = blockIdx.x * 8;
    const int tid = threadIdx.x;
    const int lane = tid & 31, w = tid >> 5;

    // ---- A: stage positions ----
#pragma unroll
    for (int p = 0; p < 2; p++) {
        int i = tid + p * 512;
        float2 pt = *(const float2*)(xabs + 2 * i);
        sf[MG_SX + i] = pt.x;
        sf[MG_SY + i] = pt.y;
    }
    // ---- WoT early (overlaps with scan latency) ----
    for (int i = tid; i < 120 * 32; i += 512) {
        int c = i >> 5, k4 = i & 31;
        float4 v = *(const float4*)(Wout + c * 128 + k4 * 4);
        sf[MG_WOT + (k4 * 4 + 0) * KD_WOT_PAD + c] = v.x;
        sf[MG_WOT + (k4 * 4 + 1) * KD_WOT_PAD + c] = v.y;
        sf[MG_WOT + (k4 * 4 + 2) * KD_WOT_PAD + c] = v.z;
        sf[MG_WOT + (k4 * 4 + 3) * KD_WOT_PAD + c] = v.w;
    }
    // ---- B: emb -> xinT[k<64][r] ----
    {
        int r = tid >> 6, e = tid & 63;
        int n = m0 + r;
        float v = b_emb[e];
        v = fmaf(xoff[2 * n + 0], W_emb[2 * e + 0], v);
        v = fmaf(xoff[2 * n + 1], W_emb[2 * e + 1], v);
        sf[MG_XINT + e * 8 + r] = fmaxf(v, 0.0f);
    }
    __syncthreads();

    // ---- C: per-agent neighbor scan + gather (2 warps per agent) ----
    const int a = w >> 1;               // agent 0..7
    const int h = w & 1;                // half of m-range
    const int n = m0 + a;
    const float xn = sf[MG_SX + n] - 0.2f;
    const float yn = sf[MG_SY + n] - 0.2f;
    const int lbase = a * 1024 + h * 512;

    unsigned cnt = 0;
#pragma unroll
    for (int t = 0; t < 16; t++) {
        int m = h * 512 + t * 32 + lane;
        float dx = sf[MG_SX + m] - xn;
        float dy = sf[MG_SY + m] - yn;
        bool v = (m != n) && dx >= 0.0f && dx < 0.4f && dy >= 0.0f && dy < 0.4f;
        int cell = 0;
        if (v) {
            int cx = (int)floorf(dx * 20.0f);
            int cy = (int)floorf(dy * 20.0f);
            v = (cx >= 0) && (cx < 8) && (cy >= 0) && (cy < 8);
            cell = cx + cy * 8;
        }
        unsigned mask = __ballot_sync(0xffffffffu, v);
        if (v) {
            int pos = cnt + __popc(mask & ((1u << lane) - 1u));
            list[lbase + pos] = (unsigned short)((m << 6) | cell);
        }
        cnt += __popc(mask);
    }
    // gather (warp reads only its own list; no block sync needed)
    float2 accA = make_float2(0.0f, 0.0f);
    float2 accB = make_float2(0.0f, 0.0f);
    int i = 0;
    for (; i + 1 < (int)cnt; i += 2) {
        unsigned v0 = list[lbase + i];
        unsigned v1 = list[lbase + i + 1];
        float2 t0 = *(const float2*)(g_Hs + (v0 >> 6) * 4096 + (v0 & 63) * 64 + lane * 2);
        float2 t1 = *(const float2*)(g_Hs + (v1 >> 6) * 4096 + (v1 & 63) * 64 + lane * 2);
        accA.x += t0.x; accA.y += t0.y;
        accB.x += t1.x; accB.y += t1.y;
    }
    if (i < (int)cnt) {
        unsigned v0 = list[lbase + i];
        float2 t0 = *(const float2*)(g_Hs + (v0 >> 6) * 4096 + (v0 & 63) * 64 + lane * 2);
        accA.x += t0.x; accA.y += t0.y;
    }
    *(float2*)&sf[MG_RED + w * 64 + lane * 2] =
        make_float2(accA.x + accB.x, accA.y + accB.y);
    __syncthreads();

    // pool combine -> xinT[64+e][r]
    {
        int r = tid >> 6, e = tid & 63;
        float sum = sf[MG_RED + (2 * r) * 64 + e] + sf[MG_RED + (2 * r + 1) * 64 + e]
                    + b_soc[e];
        sf[MG_XINT + (64 + e) * 8 + r] = fmaxf(sum, 0.0f);
    }
    __syncthreads();

    // ---- D: gatesA for this block's 8 rows; thread owns col c=tid ----
    float gA[8];
#pragma unroll
    for (int r = 0; r < 8; r++) gA[r] = 0.0f;
#pragma unroll 4
    for (int k = 0; k < 128; k++) {
        float wv = g_WihT[k * 512 + tid];
        float4 x0 = *(const float4*)&sf[MG_XINT + k * 8];
        float4 x1 = *(const float4*)&sf[MG_XINT + k * 8 + 4];
        gA[0] = fmaf(x0.x, wv, gA[0]);
        gA[1] = fmaf(x0.y, wv, gA[1]);
        gA[2] = fmaf(x0.z, wv, gA[2]);
        gA[3] = fmaf(x0.w, wv, gA[3]);
        gA[4] = fmaf(x1.x, wv, gA[4]);
        gA[5] = fmaf(x1.y, wv, gA[5]);
        gA[6] = fmaf(x1.z, wv, gA[6]);
        gA[7] = fmaf(x1.w, wv, gA[7]);
    }
    {
        float bias = b_ih[tid] + b_hh[tid];
#pragma unroll
        for (int r = 0; r < 8; r++)
            sf[MG_GATES + r * 512 + tid] =
                gA[r] + g_gatesB[(m0 + r) * 512 + tid] + bias;
    }
    __syncthreads();

    // ---- E: LSTM elementwise -> Hn ----
#pragma unroll
    for (int p = 0; p < 2; p++) {
        int id = tid + p * 512;
        int r = id >> 7, k = id & 127;
        const float* gr = &sf[MG_GATES + r * 512];
        float iv = gr[k];
        float fv = gr[128 + k];
        float gv = gr[256 + k];
        float ov = gr[384 + k];
        float si = sigmoid_ap(iv);
        float sfg = sigmoid_ap(fv);
        float so = sigmoid_ap(ov);
        float c = sfg * c0v[(m0 + r) * 128 + k] + si * tanh_ap(gv);
        sf[MG_HN + r * 128 + k] = so * tanh_ap(c);
    }
    __syncthreads();

    // ---- F: out GEMM: thread = (col tx, rows 2ty, 2ty+1) ----
    const int ty = tid >> 7;            // 0..3
    const int tx = tid & 127;           // col (active < 120)
    if (tx < 120) {
        const float* h0r = &sf[MG_HN + (ty * 2 + 0) * 128];
        const float* h1r = &sf[MG_HN + (ty * 2 + 1) * 128];
        float acc0 = 0.0f, acc1 = 0.0f;
#pragma unroll 8
        for (int k = 0; k < 128; k++) {
            float b = sf[MG_WOT + k * KD_WOT_PAD + tx];
            acc0 = fmaf(h0r[k], b, acc0);
            acc1 = fmaf(h1r[k], b, acc1);
        }
        float bo = b_out[tx];
        int cdiv = tx / 20, cmod = tx % 20;
        int n0 = m0 + ty * 2;
        out[cdiv * (NAGT * NMIX) + n0 * NMIX + cmod]       = acc0 + bo;
        out[cdiv * (NAGT * NMIX) + (n0 + 1) * NMIX + cmod] = acc1 + bo;
    }
}

// ---------------- launch ----------------
extern "C" void kernel_launch(void* const* d_in, const int* in_sizes, int n_in,
                              void* d_out, int out_size) {
    const float* xoff  = (const float*)d_in[0];
    const float* xabs  = (const float*)d_in[1];
    const float* h0    = (const float*)d_in[2];
    const float* c0    = (const float*)d_in[3];
    const float* W_emb = (const float*)d_in[4];
    const float* b_emb = (const float*)d_in[5];
    const float* W_soc = (const float*)d_in[6];
    const float* b_soc = (const float*)d_in[7];
    const float* W_ih  = (const float*)d_in[8];
    const float* W_hh  = (const float*)d_in[9];
    const float* b_ih  = (const float*)d_in[10];
    const float* b_hh  = (const float*)d_in[11];
    const float* W_out = (const float*)d_in[12];
    const float* b_out = (const float*)d_in[13];
    float* out = (float*)d_out;

    cudaFuncSetAttribute(kA, cudaFuncAttributeMaxDynamicSharedMemorySize, HS_SMEM);
    cudaFuncSetAttribute(kD, cudaFuncAttributeMaxDynamicSharedMemorySize, MG_SMEM);

    kA<<<136, 512, HS_SMEM>>>(h0, W_soc, W_hh, W_ih);
    kD<<<128, 512, MG_SMEM>>>(c0, b_ih, b_hh, W_out, b_out,
                              xoff, xabs, W_emb, b_emb, b_soc, out);
}